// round 11
// baseline (speedup 1.0000x reference)
#include <cuda_runtime.h>

#define GN 4096   // N*N
#define TT 168    // T
#define BB 128    // B
#define NN 64     // N
#define PP 128    // P

#define ROWS_PER_BLK 8
#define NBLK (GN / ROWS_PER_BLK)           // 512 blocks, single wave

// Scratch + sync (allocation-free rule: __device__ globals; zero at load,
// self-resetting each replay)
__device__ float d_yt[NN * BB];   // y transposed: y_t[j*BB + b]
__device__ int   d_y_done;
__device__ int   d_s_done;

__device__ __forceinline__ float dot4(float4 a, float4 b) {
    return a.x * b.x + a.y * b.y + a.z * b.z + a.w * b.w;
}

// ---------------------------------------------------------------------------
// ONE kernel, 512 identical blocks (single co-resident wave), three phases:
//  Y:   block m computes y rows j=(m&3)*16..+16 of batch b=m>>2
//       (x DRAM traffic spread over ALL blocks — no dedicated helper blocks),
//       blocks m<32 zero Z; fence; signal y_done.
//  MV:  rows 8m..8m+7: w^2 staged in smem, warp-per-row dot over g (L2),
//       fused F epilogue. v kept in smem (no d_v global at all).
//  SC:  gate y_done==512 (passes instantly: all signals landed ~3us before
//       any gate is reached; no block ever parks while others need slots),
//       then scatter this block's 8 v*y terms into Z[b, i=m>>3] via
//       spread-address atomicAdd (REDG-rate).
// ---------------------------------------------------------------------------
__global__ void __launch_bounds__(256) k_all(const float* __restrict__ g,
                                             const float* __restrict__ w,
                                             const float* __restrict__ alphas,
                                             const float* __restrict__ x,
                                             const int*   __restrict__ xi,
                                             float* __restrict__ Fout,
                                             float* __restrict__ Zout) {
    __shared__ __align__(16) float ws[GN];   // Y-phase: ap | MV-phase: w^2
    __shared__ float sal[TT];
    __shared__ float vsh[ROWS_PER_BLK];

    const int m    = blockIdx.x;
    const int tid  = threadIdx.x;
    const int wid  = tid >> 5;
    const int lane = tid & 31;

    // ================= Phase Y =================
    {
        const int b   = m >> 2;
        const int j0y = (m & 3) * 16;
        float* ap = ws;
        if (tid < PP)
            ap[tid] = alphas[xi[b * PP + tid]];
        if (m < 32)
            Zout[m * 256 + tid] = 0.f;      // zero Z (d_out is poisoned)
        __syncthreads();

        #pragma unroll
        for (int s2 = 0; s2 < 2; s2++) {
            const int j = j0y + wid * 2 + s2;
            const float* __restrict__ xr = x + ((size_t)b * NN + j) * PP;
            float s = xr[lane]      * ap[lane]
                    + xr[lane + 32] * ap[lane + 32]
                    + xr[lane + 64] * ap[lane + 64]
                    + xr[lane + 96] * ap[lane + 96];
            #pragma unroll
            for (int o = 16; o > 0; o >>= 1)
                s += __shfl_xor_sync(0xffffffffu, s, o);
            if (lane == 0) d_yt[j * BB + b] = s;
        }
        __syncthreads();
        if (tid == 0) {
            __threadfence();
            atomicAdd(&d_y_done, 1);
        }
        __syncthreads();   // ap dead before ws is overwritten below
    }

    // ================= Phase MV =================
    {
        const float4* __restrict__ w4g = reinterpret_cast<const float4*>(w);
        float4* ws4 = reinterpret_cast<float4*>(ws);
        #pragma unroll
        for (int k = 0; k < 4; k++) {
            float4 t = w4g[tid + k * 256];
            t.x *= t.x; t.y *= t.y; t.z *= t.z; t.w *= t.w;
            ws4[tid + k * 256] = t;
        }
        if (tid < TT) sal[tid] = alphas[tid];
        __syncthreads();

        const int row = m * ROWS_PER_BLK + wid;
        const float4* __restrict__ g4 =
            reinterpret_cast<const float4*>(g + (size_t)row * GN);

        float acc0 = 0.f, acc1 = 0.f, acc2 = 0.f, acc3 = 0.f;
        #pragma unroll
        for (int c = 0; c < 8; c++) {
            const int base = c * 128 + lane;          // float4 units
            float4 a0 = g4[base];       float4 a1 = g4[base + 32];
            float4 a2 = g4[base + 64];  float4 a3 = g4[base + 96];
            float4 b0 = ws4[base];      float4 b1 = ws4[base + 32];
            float4 b2 = ws4[base + 64]; float4 b3 = ws4[base + 96];
            acc0 += dot4(a0, b0);
            acc1 += dot4(a1, b1);
            acc2 += dot4(a2, b2);
            acc3 += dot4(a3, b3);
        }
        float s = (acc0 + acc1) + (acc2 + acc3);
        #pragma unroll
        for (int o = 16; o > 0; o >>= 1)
            s += __shfl_xor_sync(0xffffffffu, s, o);   // all lanes get sum

        // F epilogue: F[row, t] = v * alpha[t]
        float* __restrict__ Frow = Fout + (size_t)row * TT;
        #pragma unroll
        for (int t = lane; t < TT; t += 32)
            Frow[t] = s * sal[t];

        if (lane == 0) vsh[wid] = s;                   // keep v in smem
    }

    // ================= Phase SC =================
    __syncthreads();
    if (tid == 0) {
        while (atomicAdd(&d_y_done, 0) < NBLK)
            __nanosleep(64);
        __threadfence();
    }
    __syncthreads();

    if (tid < BB) {
        const int i  = m >> 3;                 // Z column this block feeds
        const int j0 = (m & 7) * ROWS_PER_BLK; // its 8 j's
        const float* __restrict__ yt = d_yt + j0 * BB + tid;   // b = tid
        float c = vsh[0] * yt[0]
                + vsh[1] * yt[BB]
                + vsh[2] * yt[2 * BB]
                + vsh[3] * yt[3 * BB]
                + vsh[4] * yt[4 * BB]
                + vsh[5] * yt[5 * BB]
                + vsh[6] * yt[6 * BB]
                + vsh[7] * yt[7 * BB];
        atomicAdd(&Zout[tid * NN + i], c);     // spread addresses -> REDG
    }

    // reset counters for next graph replay (all gates already passed)
    if (tid == 0) {
        if (atomicAdd(&d_s_done, 1) == NBLK - 1) {
            atomicExch(&d_s_done, 0);
            atomicExch(&d_y_done, 0);
        }
    }
}

// ---------------------------------------------------------------------------
extern "C" void kernel_launch(void* const* d_in, const int* in_sizes, int n_in,
                              void* d_out, int out_size) {
    const float* x      = (const float*)d_in[0];   // [B, N, P]
    const int*   xi     = (const int*)  d_in[1];   // [B, P]
    const float* g      = (const float*)d_in[2];   // [N*N, N*N]
    const float* w      = (const float*)d_in[3];   // [N*N, 1]
    const float* alphas = (const float*)d_in[4];   // [1, T]

    float* out = (float*)d_out;
    float* Z = out;               // [B, N]   = 8192
    float* F = out + BB * NN;     // [N*N, T] = 688128

    k_all<<<NBLK, 256>>>(g, w, alphas, x, xi, F, Z);
}

// round 12
// speedup vs baseline: 1.0288x; 1.0288x over previous
#include <cuda_runtime.h>

#define GN 4096   // N*N
#define TT 168    // T
#define BB 128    // B
#define NN 64     // N
#define PP 128    // P

#define ROWS_PER_BLK 8
#define MV_BLOCKS (GN / ROWS_PER_BLK)      // 512
#define TOTAL_K1  (MV_BLOCKS + BB)         // 640

// Scratch + sync (allocation-free rule: __device__ globals; zero at load,
// self-resetting every replay)
__device__ float d_v[GN];
__device__ float d_y[BB * NN];
__device__ int   d_done;     // k_main block completions (0..640)
__device__ int   d_zcnt;     // k_z block completions (reset logic)

__device__ __forceinline__ float dot4(float4 a, float4 b) {
    return a.x * b.x + a.y * b.y + a.z * b.z + a.w * b.w;
}

__device__ __forceinline__ int ld_flag(const int* p) {
    int v;
    asm volatile("ld.global.cg.b32 %0, [%1];" : "=r"(v) : "l"(p) : "memory");
    return v;
}

// ---------------------------------------------------------------------------
// Kernel 1 (R4 hot path, proven ~8us):
//  blocks [0, 512):  matvec, 8 rows/block, warp-per-row, w^2 staged in smem.
//                    Fused F epilogue; v -> d_v.
//  blocks [512, 640): per-batch y[b,j] = sum_p x[b,j,p]*alpha[x_i[b,p]].
// Every block: __syncthreads -> fence -> RED-increment d_done (no return
// value -> REDG, ~0.85cyc/op; no atomic-ALU hot spot).
// ---------------------------------------------------------------------------
__global__ void __launch_bounds__(256) k_main(const float* __restrict__ g,
                                              const float* __restrict__ w,
                                              const float* __restrict__ alphas,
                                              const float* __restrict__ x,
                                              const int*   __restrict__ xi,
                                              float* __restrict__ Fout) {
    __shared__ __align__(16) float ws[GN];   // matvec: w^2 | y-block: ap reuse
    __shared__ float sal[TT];

    const int blk  = blockIdx.x;
    const int tid  = threadIdx.x;
    const int wid  = tid >> 5;
    const int lane = tid & 31;

    if (blk < MV_BLOCKS) {
        // ---- stage w^2 (16 KB) + alphas into smem ----
        const float4* __restrict__ w4g = reinterpret_cast<const float4*>(w);
        float4* ws4 = reinterpret_cast<float4*>(ws);
        #pragma unroll
        for (int k = 0; k < 4; k++) {
            float4 t = w4g[tid + k * 256];
            t.x *= t.x; t.y *= t.y; t.z *= t.z; t.w *= t.w;
            ws4[tid + k * 256] = t;
        }
        if (tid < TT) sal[tid] = alphas[tid];
        __syncthreads();

        // ---- warp-per-row dot product ----
        const int row = blk * ROWS_PER_BLK + wid;
        const float4* __restrict__ g4 =
            reinterpret_cast<const float4*>(g + (size_t)row * GN);

        float acc0 = 0.f, acc1 = 0.f, acc2 = 0.f, acc3 = 0.f;
        #pragma unroll
        for (int c = 0; c < 8; c++) {
            const int base = c * 128 + lane;          // float4 units
            float4 a0 = g4[base];       float4 a1 = g4[base + 32];
            float4 a2 = g4[base + 64];  float4 a3 = g4[base + 96];
            float4 b0 = ws4[base];      float4 b1 = ws4[base + 32];
            float4 b2 = ws4[base + 64]; float4 b3 = ws4[base + 96];
            acc0 += dot4(a0, b0);
            acc1 += dot4(a1, b1);
            acc2 += dot4(a2, b2);
            acc3 += dot4(a3, b3);
        }
        float s = (acc0 + acc1) + (acc2 + acc3);
        #pragma unroll
        for (int o = 16; o > 0; o >>= 1)
            s += __shfl_xor_sync(0xffffffffu, s, o);   // all lanes get sum

        if (lane == 0) d_v[row] = s;

        // ---- F epilogue: F[row, t] = v * alpha[t] ----
        float* __restrict__ Frow = Fout + (size_t)row * TT;
        #pragma unroll
        for (int t = lane; t < TT; t += 32)
            Frow[t] = s * sal[t];
    } else {
        // ---- y-block: batch b ----
        const int b = blk - MV_BLOCKS;
        float* ap = ws;   // reuse smem
        if (tid < PP)
            ap[tid] = alphas[xi[b * PP + tid]];
        __syncthreads();

        #pragma unroll
        for (int j = wid; j < NN; j += 8) {
            const float* __restrict__ xr = x + ((size_t)b * NN + j) * PP;
            float s = xr[lane]      * ap[lane]
                    + xr[lane + 32] * ap[lane + 32]
                    + xr[lane + 64] * ap[lane + 64]
                    + xr[lane + 96] * ap[lane + 96];
            #pragma unroll
            for (int o = 16; o > 0; o >>= 1)
                s += __shfl_xor_sync(0xffffffffu, s, o);
            if (lane == 0) d_y[b * NN + j] = s;
        }
    }

    // ---- publish + signal (RED: result discarded) ----
    __syncthreads();
    if (tid == 0) {
        __threadfence();
        atomicAdd(&d_done, 1);
    }
}

// ---------------------------------------------------------------------------
// Kernel 2 (concurrent stream): Z[b,i] = sum_j v[i*64+j] * y[b,j]
// Launched on a forked stream -> starts at t=0, blocks resident while k_main
// runs; launch overhead fully hidden. Gate = plain cached load of d_done
// (no atomic-ALU traffic) with nanosleep backoff. After release: one output
// per 4-thread quad, 8 independent float4 loads, ~0.5us.
// ---------------------------------------------------------------------------
__global__ void __launch_bounds__(256) k_z(float* __restrict__ Zout) {
    const int b   = blockIdx.x;
    const int tid = threadIdx.x;
    const int i   = tid >> 2;      // output row 0..63
    const int q   = tid & 3;       // j-segment 0..3

    if (tid == 0) {
        while (ld_flag(&d_done) < TOTAL_K1)
            __nanosleep(256);
        __threadfence();           // acquire
    }
    __syncthreads();

    const float4* __restrict__ v4 =
        reinterpret_cast<const float4*>(d_v) + i * 16 + q * 4;
    const float4* __restrict__ y4 =
        reinterpret_cast<const float4*>(d_y) + b * 16 + q * 4;

    float4 a0 = v4[0]; float4 a1 = v4[1]; float4 a2 = v4[2]; float4 a3 = v4[3];
    float4 b0 = y4[0]; float4 b1 = y4[1]; float4 b2 = y4[2]; float4 b3 = y4[3];

    float s = (dot4(a0, b0) + dot4(a1, b1)) + (dot4(a2, b2) + dot4(a3, b3));
    s += __shfl_xor_sync(0xffffffffu, s, 1);
    s += __shfl_xor_sync(0xffffffffu, s, 2);

    if (q == 0)
        Zout[b * NN + i] = s;

    // last k_z block resets counters for the next graph replay
    __syncthreads();
    if (tid == 0) {
        if (atomicAdd(&d_zcnt, 1) == BB - 1) {
            atomicExch(&d_zcnt, 0);
            atomicExch(&d_done, 0);
        }
    }
}

// ---------------------------------------------------------------------------
extern "C" void kernel_launch(void* const* d_in, const int* in_sizes, int n_in,
                              void* d_out, int out_size) {
    const float* x      = (const float*)d_in[0];   // [B, N, P]
    const int*   xi     = (const int*)  d_in[1];   // [B, P]
    const float* g      = (const float*)d_in[2];   // [N*N, N*N]
    const float* w      = (const float*)d_in[3];   // [N*N, 1]
    const float* alphas = (const float*)d_in[4];   // [1, T]

    float* out = (float*)d_out;
    float* Z = out;               // [B, N]   = 8192
    float* F = out + BB * NN;     // [N*N, T] = 688128

    // One-time creation of side stream + events (outside capture: first call
    // is the uncaptured correctness run). No device memory involved.
    static cudaStream_t s2 = nullptr;
    static cudaEvent_t  ev_fork = nullptr, ev_join = nullptr;
    if (s2 == nullptr) {
        cudaStreamCreateWithFlags(&s2, cudaStreamNonBlocking);
        cudaEventCreateWithFlags(&ev_fork, cudaEventDisableTiming);
        cudaEventCreateWithFlags(&ev_join, cudaEventDisableTiming);
    }

    // Fork: k_z's branch depends only on the pre-k_main state -> in the
    // captured graph, k_main and k_z are PARALLEL nodes.
    cudaEventRecord(ev_fork, 0);
    cudaStreamWaitEvent(s2, ev_fork, 0);

    k_main<<<TOTAL_K1, 256, 0, 0>>>(g, w, alphas, x, xi, F);
    k_z<<<BB, 256, 0, s2>>>(Z);

    // Join back into the capture stream.
    cudaEventRecord(ev_join, s2);
    cudaStreamWaitEvent(0, ev_join, 0);
}

// round 13
// speedup vs baseline: 1.1600x; 1.1275x over previous
#include <cuda_runtime.h>

#define GN 4096   // N*N
#define TT 168    // T
#define BB 128    // B
#define NN 64     // N
#define PP 128    // P

#define ROWS_PER_BLK 16
#define MV_BLOCKS (GN / ROWS_PER_BLK)      // 256
#define YB_BATCH  4
#define Y_BLOCKS  (BB / YB_BATCH)          // 32
#define TOTAL_K1  (MV_BLOCKS + Y_BLOCKS)   // 288

#define TT4 (TT / 4)                       // 42 float4 per F row

// Scratch (allocation-free rule: __device__ globals)
__device__ float d_v[GN];
__device__ float d_y[BB * NN];

__device__ __forceinline__ float dot4(float4 a, float4 b) {
    return a.x * b.x + a.y * b.y + a.z * b.z + a.w * b.w;
}

// L1-bypass 128-bit load (g has zero reuse; keep L1 out of the path)
__device__ __forceinline__ float4 ldcg4(const float4* p) {
    float4 v;
    asm volatile("ld.global.cg.v4.f32 {%0,%1,%2,%3}, [%4];"
                 : "=f"(v.x), "=f"(v.y), "=f"(v.z), "=f"(v.w) : "l"(p));
    return v;
}

// ---------------------------------------------------------------------------
// Kernel 1 (512 threads):
//  blocks [0, 256):  matvec, 16 rows/block, warp-per-row, w^2 staged in smem
//                    once per block (w traffic 4 MB, was 8). g via __ldcg.
//                    F epilogue vectorized to STG.128.
//  blocks [256, 288): y for 4 batches: y[b,j] = sum_p x[b,j,p]*alpha[xi[b,p]].
// ---------------------------------------------------------------------------
__global__ void __launch_bounds__(512) k_main(const float* __restrict__ g,
                                              const float* __restrict__ w,
                                              const float* __restrict__ alphas,
                                              const float* __restrict__ x,
                                              const int*   __restrict__ xi,
                                              float* __restrict__ Fout) {
    __shared__ __align__(16) float ws[GN];     // matvec: w^2 | y-block: ap
    __shared__ __align__(16) float sal[TT + 8];

    const int blk  = blockIdx.x;
    const int tid  = threadIdx.x;
    const int wid  = tid >> 5;
    const int lane = tid & 31;

    if (blk < MV_BLOCKS) {
        // ---- stage w^2 (16 KB) + alphas into smem ----
        const float4* __restrict__ w4g = reinterpret_cast<const float4*>(w);
        float4* ws4 = reinterpret_cast<float4*>(ws);
        #pragma unroll
        for (int k = 0; k < 2; k++) {
            float4 t = w4g[tid + k * 512];
            t.x *= t.x; t.y *= t.y; t.z *= t.z; t.w *= t.w;
            ws4[tid + k * 512] = t;
        }
        if (tid < TT) sal[tid] = alphas[tid];
        __syncthreads();

        // ---- warp-per-row dot product (row = blk*16 + wid) ----
        const int row = blk * ROWS_PER_BLK + wid;
        const float4* __restrict__ g4 =
            reinterpret_cast<const float4*>(g + (size_t)row * GN);

        float acc0 = 0.f, acc1 = 0.f, acc2 = 0.f, acc3 = 0.f;
        #pragma unroll
        for (int c = 0; c < 8; c++) {
            const int base = c * 128 + lane;          // float4 units
            float4 a0 = ldcg4(g4 + base);
            float4 a1 = ldcg4(g4 + base + 32);
            float4 a2 = ldcg4(g4 + base + 64);
            float4 a3 = ldcg4(g4 + base + 96);
            float4 b0 = ws4[base];      float4 b1 = ws4[base + 32];
            float4 b2 = ws4[base + 64]; float4 b3 = ws4[base + 96];
            acc0 += dot4(a0, b0);
            acc1 += dot4(a1, b1);
            acc2 += dot4(a2, b2);
            acc3 += dot4(a3, b3);
        }
        float s = (acc0 + acc1) + (acc2 + acc3);
        #pragma unroll
        for (int o = 16; o > 0; o >>= 1)
            s += __shfl_xor_sync(0xffffffffu, s, o);   // all lanes get sum

        if (lane == 0) d_v[row] = s;

        // ---- F epilogue, vectorized: 42 STG.128 per row ----
        const float4* __restrict__ sal4 =
            reinterpret_cast<const float4*>(sal);
        float4* __restrict__ Fr4 =
            reinterpret_cast<float4*>(Fout + (size_t)row * TT);
        #pragma unroll
        for (int t = lane; t < TT4; t += 32) {
            float4 a = sal4[t];
            a.x *= s; a.y *= s; a.z *= s; a.w *= s;
            Fr4[t] = a;
        }
    } else {
        // ---- y-block: batches b0 .. b0+3 ----
        const int b0 = (blk - MV_BLOCKS) * YB_BATCH;
        float* ap = ws;   // 4 batches x 128 = 512 entries
        ap[tid] = alphas[xi[b0 * PP + tid]];
        __syncthreads();

        const int bsel = wid >> 2;           // 0..3
        const int b    = b0 + bsel;
        const int j00  = wid & 3;
        const float* __restrict__ apb = ap + bsel * PP;
        #pragma unroll
        for (int j = j00; j < NN; j += 4) {
            const float* __restrict__ xr = x + ((size_t)b * NN + j) * PP;
            float s = xr[lane]      * apb[lane]
                    + xr[lane + 32] * apb[lane + 32]
                    + xr[lane + 64] * apb[lane + 64]
                    + xr[lane + 96] * apb[lane + 96];
            #pragma unroll
            for (int o = 16; o > 0; o >>= 1)
                s += __shfl_xor_sync(0xffffffffu, s, o);
            if (lane == 0) d_y[b * NN + j] = s;
        }
    }
}

// ---------------------------------------------------------------------------
// Kernel 2: Z[b,i] = sum_j v[i*64+j] * y[b,j]
// grid 128, one output per 4-thread quad, 8 independent float4 loads.
// ---------------------------------------------------------------------------
__global__ void __launch_bounds__(256) k_z(float* __restrict__ Zout) {
    const int b   = blockIdx.x;
    const int tid = threadIdx.x;
    const int i   = tid >> 2;      // output row 0..63
    const int q   = tid & 3;       // j-segment 0..3

    const float4* __restrict__ v4 =
        reinterpret_cast<const float4*>(d_v) + i * 16 + q * 4;
    const float4* __restrict__ y4 =
        reinterpret_cast<const float4*>(d_y) + b * 16 + q * 4;

    float4 a0 = v4[0]; float4 a1 = v4[1]; float4 a2 = v4[2]; float4 a3 = v4[3];
    float4 b0 = y4[0]; float4 b1 = y4[1]; float4 b2 = y4[2]; float4 b3 = y4[3];

    float s = (dot4(a0, b0) + dot4(a1, b1)) + (dot4(a2, b2) + dot4(a3, b3));
    s += __shfl_xor_sync(0xffffffffu, s, 1);
    s += __shfl_xor_sync(0xffffffffu, s, 2);

    if (q == 0)
        Zout[b * NN + i] = s;
}

// ---------------------------------------------------------------------------
extern "C" void kernel_launch(void* const* d_in, const int* in_sizes, int n_in,
                              void* d_out, int out_size) {
    const float* x      = (const float*)d_in[0];   // [B, N, P]
    const int*   xi     = (const int*)  d_in[1];   // [B, P]
    const float* g      = (const float*)d_in[2];   // [N*N, N*N]
    const float* w      = (const float*)d_in[3];   // [N*N, 1]
    const float* alphas = (const float*)d_in[4];   // [1, T]

    float* out = (float*)d_out;
    float* Z = out;               // [B, N]   = 8192
    float* F = out + BB * NN;     // [N*N, T] = 688128

    k_main<<<TOTAL_K1, 512>>>(g, w, alphas, x, xi, F);
    k_z<<<BB, 256>>>(Z);
}